// round 2
// baseline (speedup 1.0000x reference)
#include <cuda_runtime.h>
#include <math.h>

#define D      512
#define B      256
#define FOURD  2048
#define QS     1024   // 2*D
#define CHUNK  10

// ---- scratch (no allocations allowed) ----
__device__ float g_Wcomb[FOURD * QS];   // [2048,1024] K-major: col<512 -> W_ih+W_hh, col>=512 -> W_ih
__device__ float g_bsum[FOURD];
__device__ float g_qstar[B * QS];       // [h | r]
__device__ float g_c[B * D];
__device__ float g_gates[B * FOURD];
__device__ int   g_segoff[B + 1];

__device__ __forceinline__ float sigf(float v) { return 1.0f / (1.0f + expf(-v)); }

// ---------------- segment offsets via binary search; auto-detect int32 vs int64 batch ----------------
// batch values are < 256, so an int64 layout has all high 32-bit words == 0.
// Tail test: int32 layout -> last two words are the (nonzero) max graph id;
// int64 layout -> one of the last two words is a high word == 0.
__global__ void k_segoff(const void* __restrict__ batch_raw, int N) {
    int b = threadIdx.x;
    if (b > B) return;
    const int* p32 = (const int*)batch_raw;
    bool is64 = (p32[N - 1] == 0) || (p32[N - 2] == 0);
    int lo = 0, hi = N;
    while (lo < hi) {
        int mid = (lo + hi) >> 1;
        int v = is64 ? (int)((const long long*)batch_raw)[mid] : p32[mid];
        if (v < b) lo = mid + 1; else hi = mid;
    }
    g_segoff[b] = lo;
}

// ---------------- W_comb = [W_ih[:, :D] + W_hh | W_ih[:, D:]], bsum = b_ih + b_hh ----------------
__global__ void k_wcomb(const float* __restrict__ W_ih, const float* __restrict__ W_hh,
                        const float* __restrict__ b_ih, const float* __restrict__ b_hh) {
    int i4 = blockIdx.x * blockDim.x + threadIdx.x;        // float4 index
    if (i4 < FOURD * QS / 4) {
        float4 v = ((const float4*)W_ih)[i4];
        int idx = i4 * 4;
        int k = idx & (QS - 1);
        int n = idx >> 10;
        if (k < D) {
            float4 w = *(const float4*)(W_hh + n * D + k);
            v.x += w.x; v.y += w.y; v.z += w.z; v.w += w.w;
        }
        ((float4*)g_Wcomb)[i4] = v;
    }
    if (i4 < FOURD) g_bsum[i4] = b_ih[i4] + b_hh[i4];
}

// ---------------- step 0: h,c from biases only (q_star = 0) ----------------
__global__ void k_step0(const float* __restrict__ b_ih, const float* __restrict__ b_hh) {
    int idx = blockIdx.x * blockDim.x + threadIdx.x;       // over B*D
    if (idx >= B * D) return;
    int j = idx & (D - 1);
    float gi = b_ih[j]         + b_hh[j];
    float gg = b_ih[2 * D + j] + b_hh[2 * D + j];
    float go = b_ih[3 * D + j] + b_hh[3 * D + j];
    float c  = sigf(gi) * tanhf(gg);         // f*c0 term is zero
    float h  = sigf(go) * tanhf(c);
    int b = idx >> 9;
    g_c[idx] = c;
    g_qstar[b * QS + j] = h;
}

// ---------------- LSTM elementwise for steps 1,2 (consumes g_gates) ----------------
__global__ void k_lstm_ew() {
    int idx = blockIdx.x * blockDim.x + threadIdx.x;
    if (idx >= B * D) return;
    int b = idx >> 9, j = idx & (D - 1);
    const float* g = g_gates + b * FOURD;
    float gi = g[j], gf = g[D + j], gg = g[2 * D + j], go = g[3 * D + j];
    float c = sigf(gf) * g_c[idx] + sigf(gi) * tanhf(gg);
    float h = sigf(go) * tanhf(c);
    g_c[idx] = c;
    g_qstar[b * QS + j] = h;
}

// ---------------- gates GEMM: [B,QS] @ Wcomb^T -> [B,FOURD], + bsum ----------------
#define GM 64
#define GN 32
#define GKK 32
__global__ void k_gemm_gates() {
    __shared__ __align__(16) float As[GKK][GM + 4];
    __shared__ __align__(16) float Bs[GKK][GN + 4];
    int m0 = blockIdx.y * GM;
    int n0 = blockIdx.x * GN;
    int t  = threadIdx.x;
    int tx = t & 15, ty = t >> 4;
    int lane8 = t & 7;
    int rowA  = t >> 3;                 // 0..31
    float acc[4][2] = {};

    for (int k0 = 0; k0 < QS; k0 += GKK) {
        #pragma unroll
        for (int h = 0; h < 2; h++) {
            int m = rowA + h * 32;
            float4 v = *(const float4*)(g_qstar + (m0 + m) * QS + k0 + lane8 * 4);
            As[lane8 * 4 + 0][m] = v.x; As[lane8 * 4 + 1][m] = v.y;
            As[lane8 * 4 + 2][m] = v.z; As[lane8 * 4 + 3][m] = v.w;
        }
        {
            int n = rowA;
            float4 v = *(const float4*)(g_Wcomb + (n0 + n) * QS + k0 + lane8 * 4);
            Bs[lane8 * 4 + 0][n] = v.x; Bs[lane8 * 4 + 1][n] = v.y;
            Bs[lane8 * 4 + 2][n] = v.z; Bs[lane8 * 4 + 3][n] = v.w;
        }
        __syncthreads();
        #pragma unroll
        for (int kk = 0; kk < GKK; kk++) {
            float4 a  = *(const float4*)&As[kk][ty * 4];
            float2 bb = *(const float2*)&Bs[kk][tx * 2];
            acc[0][0] += a.x * bb.x; acc[0][1] += a.x * bb.y;
            acc[1][0] += a.y * bb.x; acc[1][1] += a.y * bb.y;
            acc[2][0] += a.z * bb.x; acc[2][1] += a.z * bb.y;
            acc[3][0] += a.w * bb.x; acc[3][1] += a.w * bb.y;
        }
        __syncthreads();
    }
    #pragma unroll
    for (int i = 0; i < 4; i++) {
        #pragma unroll
        for (int j = 0; j < 2; j++) {
            int n = n0 + tx * 2 + j;
            g_gates[(m0 + ty * 4 + i) * FOURD + n] = acc[i][j] + g_bsum[n];
        }
    }
}

// ---------------- fused segment attention: one block per graph, online softmax ----------------
__global__ void k_attn(const float* __restrict__ x) {
    __shared__ __align__(16) float q_sh[D];
    __shared__ __align__(16) float xs[2][CHUNK][D];
    __shared__ float e_sh[CHUNK];
    __shared__ float w_sh[CHUNK];
    __shared__ float s_m, s_denom, s_alpha;

    int b = blockIdx.x;
    int t = threadIdx.x;
    int wid = t >> 5, lane = t & 31;

    int start = g_segoff[b], end = g_segoff[b + 1];
    int total = end - start;

    q_sh[t]       = g_qstar[b * QS + t];
    q_sh[t + 256] = g_qstar[b * QS + t + 256];
    if (t == 0) { s_m = -INFINITY; s_denom = 0.0f; s_alpha = 0.0f; }

    float r0 = 0.0f, r1 = 0.0f;
    int nchunks = (total + CHUNK - 1) / CHUNK;

    // preload chunk 0
    if (nchunks > 0) {
        int cnt0 = min(CHUNK, total);
        for (int i = t; i < cnt0 * (D / 4); i += 256) {
            int n = i / (D / 4), c = i % (D / 4);
            ((float4*)xs[0][n])[c] = ((const float4*)(x + (long long)(start + n) * D))[c];
        }
    }
    __syncthreads();

    for (int ci = 0; ci < nchunks; ci++) {
        int cbuf = ci & 1;
        int cnt = min(CHUNK, total - ci * CHUNK);

        // prefetch next chunk into the other buffer
        if (ci + 1 < nchunks) {
            int nstart = start + (ci + 1) * CHUNK;
            int ncnt = min(CHUNK, total - (ci + 1) * CHUNK);
            for (int i = t; i < ncnt * (D / 4); i += 256) {
                int n = i / (D / 4), c = i % (D / 4);
                ((float4*)xs[cbuf ^ 1][n])[c] =
                    ((const float4*)(x + (long long)(nstart + n) * D))[c];
            }
        }

        // e[n] = dot(x_n, q)  (warp per node)
        for (int n = wid; n < cnt; n += 8) {
            float s = 0.0f;
            #pragma unroll
            for (int j = 0; j < D / 32; j++) {
                int col = lane + 32 * j;
                s += xs[cbuf][n][col] * q_sh[col];
            }
            #pragma unroll
            for (int o = 16; o > 0; o >>= 1) s += __shfl_xor_sync(0xffffffffu, s, o);
            if (lane == 0) e_sh[n] = s;
        }
        __syncthreads();

        // warp 0: online-softmax scalar update
        if (wid == 0) {
            float e = (lane < cnt) ? e_sh[lane] : -INFINITY;
            float cm = e;
            #pragma unroll
            for (int o = 16; o > 0; o >>= 1) cm = fmaxf(cm, __shfl_xor_sync(0xffffffffu, cm, o));
            float sm_old = s_m;
            float newm = fmaxf(sm_old, cm);
            float w = (lane < cnt) ? expf(e - newm) : 0.0f;
            if (lane < cnt) w_sh[lane] = w;
            float ws = w;
            #pragma unroll
            for (int o = 16; o > 0; o >>= 1) ws += __shfl_xor_sync(0xffffffffu, ws, o);
            float alpha = expf(sm_old - newm);   // -inf -> 0 on first chunk
            __syncwarp();
            if (lane == 0) {
                s_denom = s_denom * alpha + ws;
                s_m = newm;
                s_alpha = alpha;
            }
        }
        __syncthreads();

        // rescale + accumulate r (each thread owns 2 columns)
        float al = s_alpha;
        r0 *= al; r1 *= al;
        for (int n = 0; n < cnt; n++) {
            float w = w_sh[n];
            r0 += w * xs[cbuf][n][t];
            r1 += w * xs[cbuf][n][t + 256];
        }
        __syncthreads();
    }

    float inv = 1.0f / (s_denom + 1e-16f);
    g_qstar[b * QS + D + t]       = r0 * inv;
    g_qstar[b * QS + D + t + 256] = r1 * inv;
}

// ---------------- projection: out[b,o] = qstar[b,:] . W_proj[o,:] + b_proj[o] ----------------
__global__ void k_proj(const float* __restrict__ Wp, const float* __restrict__ bp,
                       float* __restrict__ out) {
    int gw = (blockIdx.x * 256 + threadIdx.x) >> 5;   // global warp = output index
    int lane = threadIdx.x & 31;
    int bb = gw >> 8, o = gw & 255;
    const float* qr = g_qstar + bb * QS;
    const float* wr = Wp + o * QS;
    float s = 0.0f;
    #pragma unroll
    for (int it = 0; it < QS / 128; it++) {
        int k = lane * 4 + it * 128;
        float4 a = *(const float4*)(qr + k);
        float4 w = *(const float4*)(wr + k);
        s += a.x * w.x + a.y * w.y + a.z * w.z + a.w * w.w;
    }
    #pragma unroll
    for (int off = 16; off > 0; off >>= 1) s += __shfl_xor_sync(0xffffffffu, s, off);
    if (lane == 0) out[gw] = s + bp[o];
}

// ---------------- launch ----------------
extern "C" void kernel_launch(void* const* d_in, const int* in_sizes, int n_in,
                              void* d_out, int out_size) {
    const float* x      = (const float*)d_in[0];
    const void*  batch  = d_in[1];
    const float* W_ih   = (const float*)d_in[2];
    const float* W_hh   = (const float*)d_in[3];
    const float* b_ih   = (const float*)d_in[4];
    const float* b_hh   = (const float*)d_in[5];
    const float* W_proj = (const float*)d_in[6];
    const float* b_proj = (const float*)d_in[7];
    (void)n_in; (void)out_size;
    int N = in_sizes[1];

    k_segoff<<<1, 288>>>(batch, N);
    k_wcomb<<<(FOURD * QS / 4 + 255) / 256, 256>>>(W_ih, W_hh, b_ih, b_hh);

    // step 0 (LSTM degenerates to biases)
    k_step0<<<(B * D + 255) / 256, 256>>>(b_ih, b_hh);
    k_attn<<<B, 256>>>(x);

    // steps 1,2
    for (int s = 1; s < 3; s++) {
        k_gemm_gates<<<dim3(FOURD / GN, B / GM), 256>>>();
        k_lstm_ew<<<(B * D + 255) / 256, 256>>>();
        k_attn<<<B, 256>>>(x);
    }

    k_proj<<<(B * 256) / 8, 256>>>(W_proj, b_proj, (float*)d_out);
}

// round 3
// speedup vs baseline: 1.3098x; 1.3098x over previous
#include <cuda_runtime.h>
#include <math.h>

#define D      512
#define B      256
#define FOURD  2048
#define QS     1024   // 2*D
#define CHUNK  10
#define SPLITS 8

// ---- scratch (no allocations allowed) ----
__device__ float g_Wcomb[FOURD * QS];   // [2048,1024] K-major
__device__ float g_bsum[FOURD];
__device__ float g_qstar[B * QS];       // [h | r]
__device__ float g_c[B * D];
__device__ float g_gates[B * FOURD];
__device__ int   g_segoff[B + 1];
// split-attention partials
__device__ float g_pm[B * SPLITS];
__device__ float g_pd[B * SPLITS];
__device__ float g_pr[B * SPLITS * D];

__device__ __forceinline__ float sigf(float v) { return 1.0f / (1.0f + expf(-v)); }

// ---------------- parallel segment-boundary scan; auto-detect int32 vs int64 batch ----------------
// batch values < 256, so int64 layout => high 32-bit words are 0 (check last two words).
__global__ void k_segscan(const void* __restrict__ raw, int N) {
    const int* p32 = (const int*)raw;
    bool is64 = (p32[N - 1] == 0) || (p32[N - 2] == 0);
    int i = blockIdx.x * blockDim.x + threadIdx.x;
    if (i >= N) return;
    int cur  = is64 ? (int)((const long long*)raw)[i] : p32[i];
    if (i == 0) {
        for (int j = 0; j <= cur; j++) g_segoff[j] = 0;
    } else {
        int prev = is64 ? (int)((const long long*)raw)[i - 1] : p32[i - 1];
        for (int j = prev + 1; j <= cur; j++) g_segoff[j] = i;
    }
    if (i == N - 1) {
        for (int j = cur + 1; j <= B; j++) g_segoff[j] = N;
    }
}

// ---------------- W_comb = [W_ih[:, :D] + W_hh | W_ih[:, D:]], bsum = b_ih + b_hh ----------------
__global__ void k_wcomb(const float* __restrict__ W_ih, const float* __restrict__ W_hh,
                        const float* __restrict__ b_ih, const float* __restrict__ b_hh) {
    int i4 = blockIdx.x * blockDim.x + threadIdx.x;        // float4 index
    if (i4 < FOURD * QS / 4) {
        float4 v = ((const float4*)W_ih)[i4];
        int idx = i4 * 4;
        int k = idx & (QS - 1);
        int n = idx >> 10;
        if (k < D) {
            float4 w = *(const float4*)(W_hh + n * D + k);
            v.x += w.x; v.y += w.y; v.z += w.z; v.w += w.w;
        }
        ((float4*)g_Wcomb)[i4] = v;
    }
    if (i4 < FOURD) g_bsum[i4] = b_ih[i4] + b_hh[i4];
}

// ---------------- step 0: h,c from biases only (q_star = 0) ----------------
__global__ void k_step0(const float* __restrict__ b_ih, const float* __restrict__ b_hh) {
    int idx = blockIdx.x * blockDim.x + threadIdx.x;       // over B*D
    if (idx >= B * D) return;
    int j = idx & (D - 1);
    float gi = b_ih[j]         + b_hh[j];
    float gg = b_ih[2 * D + j] + b_hh[2 * D + j];
    float go = b_ih[3 * D + j] + b_hh[3 * D + j];
    float c  = sigf(gi) * tanhf(gg);
    float h  = sigf(go) * tanhf(c);
    int b = idx >> 9;
    g_c[idx] = c;
    g_qstar[b * QS + j] = h;
}

// ---------------- LSTM elementwise for steps 1,2 (consumes g_gates) ----------------
__global__ void k_lstm_ew() {
    int idx = blockIdx.x * blockDim.x + threadIdx.x;
    if (idx >= B * D) return;
    int b = idx >> 9, j = idx & (D - 1);
    const float* g = g_gates + b * FOURD;
    float gi = g[j], gf = g[D + j], gg = g[2 * D + j], go = g[3 * D + j];
    float c = sigf(gf) * g_c[idx] + sigf(gi) * tanhf(gg);
    float h = sigf(go) * tanhf(c);
    g_c[idx] = c;
    g_qstar[b * QS + j] = h;
}

// ---------------- gates GEMM: [B,QS] @ Wcomb^T -> [B,FOURD], + bsum ----------------
#define GM 64
#define GN 32
#define GKK 32
__global__ void k_gemm_gates() {
    __shared__ __align__(16) float As[GKK][GM + 4];
    __shared__ __align__(16) float Bs[GKK][GN + 4];
    int m0 = blockIdx.y * GM;
    int n0 = blockIdx.x * GN;
    int t  = threadIdx.x;
    int tx = t & 15, ty = t >> 4;
    int lane8 = t & 7;
    int rowA  = t >> 3;                 // 0..31
    float acc[4][2] = {};

    for (int k0 = 0; k0 < QS; k0 += GKK) {
        #pragma unroll
        for (int h = 0; h < 2; h++) {
            int m = rowA + h * 32;
            float4 v = *(const float4*)(g_qstar + (m0 + m) * QS + k0 + lane8 * 4);
            As[lane8 * 4 + 0][m] = v.x; As[lane8 * 4 + 1][m] = v.y;
            As[lane8 * 4 + 2][m] = v.z; As[lane8 * 4 + 3][m] = v.w;
        }
        {
            int n = rowA;
            float4 v = *(const float4*)(g_Wcomb + (n0 + n) * QS + k0 + lane8 * 4);
            Bs[lane8 * 4 + 0][n] = v.x; Bs[lane8 * 4 + 1][n] = v.y;
            Bs[lane8 * 4 + 2][n] = v.z; Bs[lane8 * 4 + 3][n] = v.w;
        }
        __syncthreads();
        #pragma unroll
        for (int kk = 0; kk < GKK; kk++) {
            float4 a  = *(const float4*)&As[kk][ty * 4];
            float2 bb = *(const float2*)&Bs[kk][tx * 2];
            acc[0][0] += a.x * bb.x; acc[0][1] += a.x * bb.y;
            acc[1][0] += a.y * bb.x; acc[1][1] += a.y * bb.y;
            acc[2][0] += a.z * bb.x; acc[2][1] += a.z * bb.y;
            acc[3][0] += a.w * bb.x; acc[3][1] += a.w * bb.y;
        }
        __syncthreads();
    }
    #pragma unroll
    for (int i = 0; i < 4; i++) {
        #pragma unroll
        for (int j = 0; j < 2; j++) {
            int n = n0 + tx * 2 + j;
            g_gates[(m0 + ty * 4 + i) * FOURD + n] = acc[i][j] + g_bsum[n];
        }
    }
}

// ---------------- split segment attention: one block per (graph, split), online softmax ----------------
__global__ void k_attn_part(const float* __restrict__ x) {
    __shared__ __align__(16) float q_sh[D];
    __shared__ __align__(16) float xs[2][CHUNK][D];
    __shared__ float e_sh[CHUNK];
    __shared__ float w_sh[CHUNK];
    __shared__ float s_m, s_denom, s_alpha;

    int b  = blockIdx.x / SPLITS;
    int sp = blockIdx.x % SPLITS;
    int t = threadIdx.x;
    int wid = t >> 5, lane = t & 31;

    int segs = g_segoff[b], sege = g_segoff[b + 1];
    int total = sege - segs;
    int start = segs + (int)(((long long)total * sp) / SPLITS);
    int end   = segs + (int)(((long long)total * (sp + 1)) / SPLITS);
    int cntot = end - start;

    q_sh[t]       = g_qstar[b * QS + t];
    q_sh[t + 256] = g_qstar[b * QS + t + 256];
    if (t == 0) { s_m = -INFINITY; s_denom = 0.0f; s_alpha = 0.0f; }

    float r0 = 0.0f, r1 = 0.0f;
    int nchunks = (cntot + CHUNK - 1) / CHUNK;

    // preload chunk 0
    if (nchunks > 0) {
        int cnt0 = min(CHUNK, cntot);
        for (int i = t; i < cnt0 * (D / 4); i += 256) {
            int n = i / (D / 4), c = i % (D / 4);
            ((float4*)xs[0][n])[c] = ((const float4*)(x + (long long)(start + n) * D))[c];
        }
    }
    __syncthreads();

    for (int ci = 0; ci < nchunks; ci++) {
        int cbuf = ci & 1;
        int cnt = min(CHUNK, cntot - ci * CHUNK);

        // prefetch next chunk
        if (ci + 1 < nchunks) {
            int nstart = start + (ci + 1) * CHUNK;
            int ncnt = min(CHUNK, cntot - (ci + 1) * CHUNK);
            for (int i = t; i < ncnt * (D / 4); i += 256) {
                int n = i / (D / 4), c = i % (D / 4);
                ((float4*)xs[cbuf ^ 1][n])[c] =
                    ((const float4*)(x + (long long)(nstart + n) * D))[c];
            }
        }

        // e[n] = dot(x_n, q)  (warp per node)
        for (int n = wid; n < cnt; n += 8) {
            float s = 0.0f;
            #pragma unroll
            for (int j = 0; j < D / 32; j++) {
                int col = lane + 32 * j;
                s += xs[cbuf][n][col] * q_sh[col];
            }
            #pragma unroll
            for (int o = 16; o > 0; o >>= 1) s += __shfl_xor_sync(0xffffffffu, s, o);
            if (lane == 0) e_sh[n] = s;
        }
        __syncthreads();

        // warp 0: online-softmax scalar update
        if (wid == 0) {
            float e = (lane < cnt) ? e_sh[lane] : -INFINITY;
            float cm = e;
            #pragma unroll
            for (int o = 16; o > 0; o >>= 1) cm = fmaxf(cm, __shfl_xor_sync(0xffffffffu, cm, o));
            float sm_old = s_m;
            float newm = fmaxf(sm_old, cm);
            float w = (lane < cnt) ? expf(e - newm) : 0.0f;
            if (lane < cnt) w_sh[lane] = w;
            float ws = w;
            #pragma unroll
            for (int o = 16; o > 0; o >>= 1) ws += __shfl_xor_sync(0xffffffffu, ws, o);
            float alpha = expf(sm_old - newm);   // -inf -> 0 on first chunk
            __syncwarp();
            if (lane == 0) {
                s_denom = s_denom * alpha + ws;
                s_m = newm;
                s_alpha = alpha;
            }
        }
        __syncthreads();

        // rescale + accumulate r (each thread owns 2 columns)
        float al = s_alpha;
        r0 *= al; r1 *= al;
        for (int n = 0; n < cnt; n++) {
            float w = w_sh[n];
            r0 += w * xs[cbuf][n][t];
            r1 += w * xs[cbuf][n][t + 256];
        }
        __syncthreads();
    }

    // write unnormalized partial
    int pid = b * SPLITS + sp;
    g_pr[(long long)pid * D + t]       = r0;
    g_pr[(long long)pid * D + t + 256] = r1;
    if (t == 0) { g_pm[pid] = s_m; g_pd[pid] = s_denom; }
}

// ---------------- combine split partials -> r in g_qstar ----------------
__global__ void k_attn_combine() {
    __shared__ float sm[SPLITS], sd[SPLITS];
    int b = blockIdx.x, t = threadIdx.x;
    if (t < SPLITS) {
        sm[t] = g_pm[b * SPLITS + t];
        sd[t] = g_pd[b * SPLITS + t];
    }
    __syncthreads();
    float M = -INFINITY;
    #pragma unroll
    for (int p = 0; p < SPLITS; p++) M = fmaxf(M, sm[p]);
    if (!isfinite(M)) M = 0.0f;
    float scale[SPLITS];
    float denom = 0.0f;
    #pragma unroll
    for (int p = 0; p < SPLITS; p++) {
        scale[p] = expf(sm[p] - M);
        denom += sd[p] * scale[p];
    }
    float inv = 1.0f / (denom + 1e-16f);
    float r0 = 0.0f, r1 = 0.0f;
    #pragma unroll
    for (int p = 0; p < SPLITS; p++) {
        const float* pr = g_pr + (long long)(b * SPLITS + p) * D;
        r0 += pr[t]       * scale[p];
        r1 += pr[t + 256] * scale[p];
    }
    g_qstar[b * QS + D + t]       = r0 * inv;
    g_qstar[b * QS + D + t + 256] = r1 * inv;
}

// ---------------- projection: out[b,o] = qstar[b,:] . W_proj[o,:] + b_proj[o] ----------------
__global__ void k_proj(const float* __restrict__ Wp, const float* __restrict__ bp,
                       float* __restrict__ out) {
    int gw = (blockIdx.x * 256 + threadIdx.x) >> 5;   // global warp = output index
    int lane = threadIdx.x & 31;
    int bb = gw >> 8, o = gw & 255;
    const float* qr = g_qstar + bb * QS;
    const float* wr = Wp + o * QS;
    float s = 0.0f;
    #pragma unroll
    for (int it = 0; it < QS / 128; it++) {
        int k = lane * 4 + it * 128;
        float4 a = *(const float4*)(qr + k);
        float4 w = *(const float4*)(wr + k);
        s += a.x * w.x + a.y * w.y + a.z * w.z + a.w * w.w;
    }
    #pragma unroll
    for (int off = 16; off > 0; off >>= 1) s += __shfl_xor_sync(0xffffffffu, s, off);
    if (lane == 0) out[gw] = s + bp[o];
}

// ---------------- launch ----------------
extern "C" void kernel_launch(void* const* d_in, const int* in_sizes, int n_in,
                              void* d_out, int out_size) {
    const float* x      = (const float*)d_in[0];
    const void*  batch  = d_in[1];
    const float* W_ih   = (const float*)d_in[2];
    const float* W_hh   = (const float*)d_in[3];
    const float* b_ih   = (const float*)d_in[4];
    const float* b_hh   = (const float*)d_in[5];
    const float* W_proj = (const float*)d_in[6];
    const float* b_proj = (const float*)d_in[7];
    (void)n_in; (void)out_size;
    int N = in_sizes[1];

    k_segscan<<<(N + 255) / 256, 256>>>(batch, N);
    k_wcomb<<<(FOURD * QS / 4 + 255) / 256, 256>>>(W_ih, W_hh, b_ih, b_hh);

    // step 0 (LSTM degenerates to biases)
    k_step0<<<(B * D + 255) / 256, 256>>>(b_ih, b_hh);
    k_attn_part<<<B * SPLITS, 256>>>(x);
    k_attn_combine<<<B, 256>>>();

    // steps 1,2
    for (int s = 1; s < 3; s++) {
        k_gemm_gates<<<dim3(FOURD / GN, B / GM), 256>>>();
        k_lstm_ew<<<(B * D + 255) / 256, 256>>>();
        k_attn_part<<<B * SPLITS, 256>>>(x);
        k_attn_combine<<<B, 256>>>();
    }

    k_proj<<<(B * 256) / 8, 256>>>(W_proj, b_proj, (float*)d_out);
}

// round 4
// speedup vs baseline: 1.8815x; 1.4365x over previous
#include <cuda_runtime.h>
#include <math.h>

#define D      512
#define B      256
#define FOURD  2048
#define QS     1024   // 2*D
#define SPLITS 8
#define NW     8      // warps per attn block

#define BM 128
#define BN 128
#define BK 16
#define KSPLIT 4
#define KCH (QS / KSPLIT)   // 256

// ---- scratch (no allocations allowed) ----
__device__ float g_Wcomb[FOURD * QS];   // [2048,1024] K-major
__device__ float g_bsum[FOURD];
__device__ float g_qstar[B * QS];       // [h | r]
__device__ float g_c[B * D];
__device__ float g_gpart[KSPLIT][B * FOURD];
__device__ int   g_segoff[B + 1];
// split-attention partials
__device__ float g_pm[B * SPLITS];
__device__ float g_pd[B * SPLITS];
__device__ float g_pr[B * SPLITS * D];

__device__ __forceinline__ float sigf(float v) { return 1.0f / (1.0f + expf(-v)); }

// ---------------- parallel segment-boundary scan; auto-detect int32 vs int64 batch ----------------
__global__ void k_segscan(const void* __restrict__ raw, int N) {
    const int* p32 = (const int*)raw;
    bool is64 = (p32[N - 1] == 0) || (p32[N - 2] == 0);
    int i = blockIdx.x * blockDim.x + threadIdx.x;
    if (i >= N) return;
    int cur = is64 ? (int)((const long long*)raw)[i] : p32[i];
    if (i == 0) {
        for (int j = 0; j <= cur; j++) g_segoff[j] = 0;
    } else {
        int prev = is64 ? (int)((const long long*)raw)[i - 1] : p32[i - 1];
        for (int j = prev + 1; j <= cur; j++) g_segoff[j] = i;
    }
    if (i == N - 1) {
        for (int j = cur + 1; j <= B; j++) g_segoff[j] = N;
    }
}

// ---------------- W_comb = [W_ih[:, :D] + W_hh | W_ih[:, D:]], bsum = b_ih + b_hh ----------------
__global__ void k_wcomb(const float* __restrict__ W_ih, const float* __restrict__ W_hh,
                        const float* __restrict__ b_ih, const float* __restrict__ b_hh) {
    int i4 = blockIdx.x * blockDim.x + threadIdx.x;
    if (i4 < FOURD * QS / 4) {
        float4 v = ((const float4*)W_ih)[i4];
        int idx = i4 * 4;
        int k = idx & (QS - 1);
        int n = idx >> 10;
        if (k < D) {
            float4 w = *(const float4*)(W_hh + n * D + k);
            v.x += w.x; v.y += w.y; v.z += w.z; v.w += w.w;
        }
        ((float4*)g_Wcomb)[i4] = v;
    }
    if (i4 < FOURD) g_bsum[i4] = b_ih[i4] + b_hh[i4];
}

// ---------------- step 0: h,c from biases only (q_star = 0) ----------------
__global__ void k_step0(const float* __restrict__ b_ih, const float* __restrict__ b_hh) {
    int idx = blockIdx.x * blockDim.x + threadIdx.x;
    if (idx >= B * D) return;
    int j = idx & (D - 1);
    float gi = b_ih[j]         + b_hh[j];
    float gg = b_ih[2 * D + j] + b_hh[2 * D + j];
    float go = b_ih[3 * D + j] + b_hh[3 * D + j];
    float c  = sigf(gi) * tanhf(gg);
    float h  = sigf(go) * tanhf(c);
    int b = idx >> 9;
    g_c[idx] = c;
    g_qstar[b * QS + j] = h;
}

// ---------------- LSTM elementwise for steps 1,2 (sums K-split partials + bias) ----------------
__global__ void k_lstm_ew() {
    int idx = blockIdx.x * blockDim.x + threadIdx.x;
    if (idx >= B * D) return;
    int b = idx >> 9, j = idx & (D - 1);
    float gi = g_bsum[j], gf = g_bsum[D + j], gg = g_bsum[2 * D + j], go = g_bsum[3 * D + j];
    #pragma unroll
    for (int z = 0; z < KSPLIT; z++) {
        const float* g = &g_gpart[z][(size_t)b * FOURD];
        gi += g[j]; gf += g[D + j]; gg += g[2 * D + j]; go += g[3 * D + j];
    }
    float c = sigf(gf) * g_c[idx] + sigf(gi) * tanhf(gg);
    float h = sigf(go) * tanhf(c);
    g_c[idx] = c;
    g_qstar[b * QS + j] = h;
}

// ---------------- gates GEMM: split-K, 128x128 tile, 8x8 microtile ----------------
__global__ void k_gemm_gates() {
    __shared__ __align__(16) float As[BK][BM + 4];
    __shared__ __align__(16) float Bs[BK][BN + 4];
    int n0 = blockIdx.x * BN, m0 = blockIdx.y * BM, kc = blockIdx.z * KCH;
    int t = threadIdx.x;
    int tx = t & 15, ty = t >> 4;
    float acc[8][8] = {};

    for (int k0 = 0; k0 < KCH; k0 += BK) {
        #pragma unroll
        for (int s = 0; s < 2; s++) {
            int i4 = t + s * 256;
            int row = i4 >> 2, kq = (i4 & 3) * 4;
            float4 va = *(const float4*)(g_qstar + (size_t)(m0 + row) * QS + kc + k0 + kq);
            As[kq + 0][row] = va.x; As[kq + 1][row] = va.y;
            As[kq + 2][row] = va.z; As[kq + 3][row] = va.w;
            float4 vb = *(const float4*)(g_Wcomb + (size_t)(n0 + row) * QS + kc + k0 + kq);
            Bs[kq + 0][row] = vb.x; Bs[kq + 1][row] = vb.y;
            Bs[kq + 2][row] = vb.z; Bs[kq + 3][row] = vb.w;
        }
        __syncthreads();
        #pragma unroll
        for (int kk = 0; kk < BK; kk++) {
            float a[8], bb[8];
            *(float4*)(a)      = *(const float4*)&As[kk][ty * 8];
            *(float4*)(a + 4)  = *(const float4*)&As[kk][ty * 8 + 4];
            *(float4*)(bb)     = *(const float4*)&Bs[kk][tx * 8];
            *(float4*)(bb + 4) = *(const float4*)&Bs[kk][tx * 8 + 4];
            #pragma unroll
            for (int i = 0; i < 8; i++)
                #pragma unroll
                for (int j = 0; j < 8; j++)
                    acc[i][j] += a[i] * bb[j];
        }
        __syncthreads();
    }
    #pragma unroll
    for (int i = 0; i < 8; i++) {
        int mrow = m0 + ty * 8 + i;
        float* dst = &g_gpart[blockIdx.z][(size_t)mrow * FOURD + n0 + tx * 8];
        #pragma unroll
        for (int j = 0; j < 8; j += 4)
            *(float4*)(dst + j) = make_float4(acc[i][j], acc[i][j + 1], acc[i][j + 2], acc[i][j + 3]);
    }
}

// ---------------- split segment attention: warp-autonomous online softmax ----------------
__global__ void k_attn_part(const float* __restrict__ x) {
    __shared__ __align__(16) float q_sh[D];
    __shared__ __align__(16) float rsh[NW][D];
    __shared__ float msh[NW], dsh[NW];

    int b  = blockIdx.x / SPLITS;
    int sp = blockIdx.x % SPLITS;
    int t = threadIdx.x;
    int w = t >> 5, lane = t & 31;

    int segs = g_segoff[b], sege = g_segoff[b + 1];
    int total = sege - segs;
    int start = segs + (int)(((long long)total * sp) / SPLITS);
    int end   = segs + (int)(((long long)total * (sp + 1)) / SPLITS);

    q_sh[t]       = g_qstar[b * QS + t];
    q_sh[t + 256] = g_qstar[b * QS + t + 256];
    __syncthreads();

    int cbase = lane * 16;
    float qr[16];
    #pragma unroll
    for (int j = 0; j < 16; j++) qr[j] = q_sh[cbase + j];

    float m = -INFINITY, d = 0.0f;
    float r[16];
    #pragma unroll
    for (int j = 0; j < 16; j++) r[j] = 0.0f;

    int n = start + w;
    float4 xb0, xb1, xb2, xb3;
    if (n < end) {
        const float4* p = (const float4*)(x + (size_t)n * D + cbase);
        xb0 = p[0]; xb1 = p[1]; xb2 = p[2]; xb3 = p[3];
    }
    while (n < end) {
        float4 c0 = xb0, c1 = xb1, c2 = xb2, c3 = xb3;
        int nn = n + NW;
        if (nn < end) {
            const float4* p = (const float4*)(x + (size_t)nn * D + cbase);
            xb0 = p[0]; xb1 = p[1]; xb2 = p[2]; xb3 = p[3];
        }
        float s = c0.x * qr[0]  + c0.y * qr[1]  + c0.z * qr[2]  + c0.w * qr[3]
                + c1.x * qr[4]  + c1.y * qr[5]  + c1.z * qr[6]  + c1.w * qr[7]
                + c2.x * qr[8]  + c2.y * qr[9]  + c2.z * qr[10] + c2.w * qr[11]
                + c3.x * qr[12] + c3.y * qr[13] + c3.z * qr[14] + c3.w * qr[15];
        #pragma unroll
        for (int o = 16; o > 0; o >>= 1) s += __shfl_xor_sync(0xffffffffu, s, o);

        if (s > m) {
            float al = expf(m - s);     // first iteration: exp(-inf) = 0
            d = d * al + 1.0f;          // new weight = exp(s - s) = 1
            r[0]  = r[0]  * al + c0.x;  r[1]  = r[1]  * al + c0.y;
            r[2]  = r[2]  * al + c0.z;  r[3]  = r[3]  * al + c0.w;
            r[4]  = r[4]  * al + c1.x;  r[5]  = r[5]  * al + c1.y;
            r[6]  = r[6]  * al + c1.z;  r[7]  = r[7]  * al + c1.w;
            r[8]  = r[8]  * al + c2.x;  r[9]  = r[9]  * al + c2.y;
            r[10] = r[10] * al + c2.z;  r[11] = r[11] * al + c2.w;
            r[12] = r[12] * al + c3.x;  r[13] = r[13] * al + c3.y;
            r[14] = r[14] * al + c3.z;  r[15] = r[15] * al + c3.w;
            m = s;
        } else {
            float wv = expf(s - m);
            d += wv;
            r[0]  += wv * c0.x;  r[1]  += wv * c0.y;  r[2]  += wv * c0.z;  r[3]  += wv * c0.w;
            r[4]  += wv * c1.x;  r[5]  += wv * c1.y;  r[6]  += wv * c1.z;  r[7]  += wv * c1.w;
            r[8]  += wv * c2.x;  r[9]  += wv * c2.y;  r[10] += wv * c2.z;  r[11] += wv * c2.w;
            r[12] += wv * c3.x;  r[13] += wv * c3.y;  r[14] += wv * c3.z;  r[15] += wv * c3.w;
        }
        n = nn;
    }

    // per-warp partials to shared
    if (lane == 0) { msh[w] = m; dsh[w] = d; }
    float* rw = &rsh[w][cbase];
    #pragma unroll
    for (int j = 0; j < 16; j += 4)
        *(float4*)(rw + j) = make_float4(r[j], r[j + 1], r[j + 2], r[j + 3]);
    __syncthreads();

    // block combine: thread t owns cols t and t+256
    float M = msh[0];
    #pragma unroll
    for (int p = 1; p < NW; p++) M = fmaxf(M, msh[p]);
    float Mg = isfinite(M) ? M : 0.0f;
    float dd = 0.0f, r0 = 0.0f, r1 = 0.0f;
    #pragma unroll
    for (int p = 0; p < NW; p++) {
        float sc = expf(msh[p] - Mg);
        dd += dsh[p] * sc;
        r0 += rsh[p][t] * sc;
        r1 += rsh[p][t + 256] * sc;
    }
    int pid = b * SPLITS + sp;
    g_pr[(size_t)pid * D + t]       = r0;
    g_pr[(size_t)pid * D + t + 256] = r1;
    if (t == 0) { g_pm[pid] = M; g_pd[pid] = dd; }
}

// ---------------- combine split partials -> r in g_qstar ----------------
__global__ void k_attn_combine() {
    __shared__ float sm[SPLITS], sd[SPLITS];
    int b = blockIdx.x, t = threadIdx.x;
    if (t < SPLITS) {
        sm[t] = g_pm[b * SPLITS + t];
        sd[t] = g_pd[b * SPLITS + t];
    }
    __syncthreads();
    float M = -INFINITY;
    #pragma unroll
    for (int p = 0; p < SPLITS; p++) M = fmaxf(M, sm[p]);
    if (!isfinite(M)) M = 0.0f;
    float denom = 0.0f;
    float scale[SPLITS];
    #pragma unroll
    for (int p = 0; p < SPLITS; p++) {
        scale[p] = expf(sm[p] - M);
        denom += sd[p] * scale[p];
    }
    float inv = 1.0f / (denom + 1e-16f);
    float r0 = 0.0f, r1 = 0.0f;
    #pragma unroll
    for (int p = 0; p < SPLITS; p++) {
        const float* pr = g_pr + (size_t)(b * SPLITS + p) * D;
        r0 += pr[t]       * scale[p];
        r1 += pr[t + 256] * scale[p];
    }
    g_qstar[b * QS + D + t]       = r0 * inv;
    g_qstar[b * QS + D + t + 256] = r1 * inv;
}

// ---------------- projection: out[b,o] = qstar[b,:] . W_proj[o,:] + b_proj[o] ----------------
__global__ void k_proj(const float* __restrict__ Wp, const float* __restrict__ bp,
                       float* __restrict__ out) {
    int gw = (blockIdx.x * 256 + threadIdx.x) >> 5;
    int lane = threadIdx.x & 31;
    int bb = gw >> 8, o = gw & 255;
    const float* qr = g_qstar + bb * QS;
    const float* wr = Wp + o * QS;
    float s = 0.0f;
    #pragma unroll
    for (int it = 0; it < QS / 128; it++) {
        int k = lane * 4 + it * 128;
        float4 a = *(const float4*)(qr + k);
        float4 w = *(const float4*)(wr + k);
        s += a.x * w.x + a.y * w.y + a.z * w.z + a.w * w.w;
    }
    #pragma unroll
    for (int off = 16; off > 0; off >>= 1) s += __shfl_xor_sync(0xffffffffu, s, off);
    if (lane == 0) out[gw] = s + bp[o];
}

// ---------------- launch ----------------
extern "C" void kernel_launch(void* const* d_in, const int* in_sizes, int n_in,
                              void* d_out, int out_size) {
    const float* x      = (const float*)d_in[0];
    const void*  batch  = d_in[1];
    const float* W_ih   = (const float*)d_in[2];
    const float* W_hh   = (const float*)d_in[3];
    const float* b_ih   = (const float*)d_in[4];
    const float* b_hh   = (const float*)d_in[5];
    const float* W_proj = (const float*)d_in[6];
    const float* b_proj = (const float*)d_in[7];
    (void)n_in; (void)out_size;
    int N = in_sizes[1];

    k_segscan<<<(N + 255) / 256, 256>>>(batch, N);
    k_wcomb<<<(FOURD * QS / 4 + 255) / 256, 256>>>(W_ih, W_hh, b_ih, b_hh);

    // step 0 (LSTM degenerates to biases)
    k_step0<<<(B * D + 255) / 256, 256>>>(b_ih, b_hh);
    k_attn_part<<<B * SPLITS, 256>>>(x);
    k_attn_combine<<<B, 256>>>();

    // steps 1,2
    for (int s = 1; s < 3; s++) {
        k_gemm_gates<<<dim3(FOURD / BN, B / BM, KSPLIT), 256>>>();
        k_lstm_ew<<<(B * D + 255) / 256, 256>>>();
        k_attn_part<<<B * SPLITS, 256>>>(x);
        k_attn_combine<<<B, 256>>>();
    }

    k_proj<<<(B * 256) / 8, 256>>>(W_proj, b_proj, (float*)d_out);
}

// round 5
// speedup vs baseline: 2.0291x; 1.0785x over previous
#include <cuda_runtime.h>
#include <math.h>

#define D      512
#define B      256
#define FOURD  2048
#define QS     1024   // 2*D
#define SPLITS 8
#define NW     8      // warps per attn block

#define BM 128
#define BN 128
#define BK 16
#define KSPLIT 8
#define KCH (QS / KSPLIT)   // 128

// ---- scratch (no allocations allowed) ----
__device__ float g_Wcomb[FOURD * QS];   // [2048,1024] K-major
__device__ float g_bsum[FOURD];
__device__ float g_qstar[B * QS];       // [h | r]
__device__ float g_c[B * D];
__device__ float g_gpart[KSPLIT][B * FOURD];
__device__ int   g_segoff[B + 1];
// split-attention partials
__device__ float g_pm[B * SPLITS];
__device__ float g_pd[B * SPLITS];
__device__ float g_pr[B * SPLITS * D];

__device__ __forceinline__ float sigf(float v) { return 1.0f / (1.0f + expf(-v)); }

// ---------------- parallel segment-boundary scan; auto-detect int32 vs int64 batch ----------------
__global__ void k_segscan(const void* __restrict__ raw, int N) {
    const int* p32 = (const int*)raw;
    bool is64 = (p32[N - 1] == 0) || (p32[N - 2] == 0);
    int i = blockIdx.x * blockDim.x + threadIdx.x;
    if (i >= N) return;
    int cur = is64 ? (int)((const long long*)raw)[i] : p32[i];
    if (i == 0) {
        for (int j = 0; j <= cur; j++) g_segoff[j] = 0;
    } else {
        int prev = is64 ? (int)((const long long*)raw)[i - 1] : p32[i - 1];
        for (int j = prev + 1; j <= cur; j++) g_segoff[j] = i;
    }
    if (i == N - 1) {
        for (int j = cur + 1; j <= B; j++) g_segoff[j] = N;
    }
}

// ---------------- W_comb = [W_ih[:, :D] + W_hh | W_ih[:, D:]], bsum = b_ih + b_hh ----------------
__global__ void k_wcomb(const float* __restrict__ W_ih, const float* __restrict__ W_hh,
                        const float* __restrict__ b_ih, const float* __restrict__ b_hh) {
    int i4 = blockIdx.x * blockDim.x + threadIdx.x;
    if (i4 < FOURD * QS / 4) {
        float4 v = ((const float4*)W_ih)[i4];
        int idx = i4 * 4;
        int k = idx & (QS - 1);
        int n = idx >> 10;
        if (k < D) {
            float4 w = *(const float4*)(W_hh + n * D + k);
            v.x += w.x; v.y += w.y; v.z += w.z; v.w += w.w;
        }
        ((float4*)g_Wcomb)[i4] = v;
    }
    if (i4 < FOURD) g_bsum[i4] = b_ih[i4] + b_hh[i4];
}

// ---------------- step 0: h,c from biases only (q_star = 0) ----------------
__global__ void k_step0(const float* __restrict__ b_ih, const float* __restrict__ b_hh) {
    int idx = blockIdx.x * blockDim.x + threadIdx.x;
    if (idx >= B * D) return;
    int j = idx & (D - 1);
    float gi = b_ih[j]         + b_hh[j];
    float gg = b_ih[2 * D + j] + b_hh[2 * D + j];
    float go = b_ih[3 * D + j] + b_hh[3 * D + j];
    float c  = sigf(gi) * tanhf(gg);
    float h  = sigf(go) * tanhf(c);
    int b = idx >> 9;
    g_c[idx] = c;
    g_qstar[b * QS + j] = h;
}

// ---------------- LSTM elementwise for steps 1,2 (sums K-split partials + bias) ----------------
__global__ void k_lstm_ew() {
    int idx = blockIdx.x * blockDim.x + threadIdx.x;
    if (idx >= B * D) return;
    int b = idx >> 9, j = idx & (D - 1);
    float gi = g_bsum[j], gf = g_bsum[D + j], gg = g_bsum[2 * D + j], go = g_bsum[3 * D + j];
    #pragma unroll
    for (int z = 0; z < KSPLIT; z++) {
        const float* g = &g_gpart[z][(size_t)b * FOURD];
        gi += g[j]; gf += g[D + j]; gg += g[2 * D + j]; go += g[3 * D + j];
    }
    float c = sigf(gf) * g_c[idx] + sigf(gi) * tanhf(gg);
    float h = sigf(go) * tanhf(c);
    g_c[idx] = c;
    g_qstar[b * QS + j] = h;
}

// ---------------- gates GEMM: split-K, 128x128 tile, 8x8 microtile, packed f32x2 FMA ----------------
__global__ void __launch_bounds__(256) k_gemm_gates() {
    __shared__ __align__(16) float As[BK][BM + 4];
    __shared__ __align__(16) float Bs[BK][BN + 4];
    int n0 = blockIdx.x * BN, m0 = blockIdx.y * BM, kc = blockIdx.z * KCH;
    int t = threadIdx.x;
    int tx = t & 15, ty = t >> 4;
    unsigned long long acc2[8][4];
    #pragma unroll
    for (int i = 0; i < 8; i++)
        #pragma unroll
        for (int j = 0; j < 4; j++) acc2[i][j] = 0ull;   // {0.0f, 0.0f}

    for (int k0 = 0; k0 < KCH; k0 += BK) {
        #pragma unroll
        for (int s = 0; s < 2; s++) {
            int i4 = t + s * 256;
            int row = i4 >> 2, kq = (i4 & 3) * 4;
            float4 va = *(const float4*)(g_qstar + (size_t)(m0 + row) * QS + kc + k0 + kq);
            As[kq + 0][row] = va.x; As[kq + 1][row] = va.y;
            As[kq + 2][row] = va.z; As[kq + 3][row] = va.w;
            float4 vb = *(const float4*)(g_Wcomb + (size_t)(n0 + row) * QS + kc + k0 + kq);
            Bs[kq + 0][row] = vb.x; Bs[kq + 1][row] = vb.y;
            Bs[kq + 2][row] = vb.z; Bs[kq + 3][row] = vb.w;
        }
        __syncthreads();
        #pragma unroll
        for (int kk = 0; kk < BK; kk++) {
            float a[8];
            *(float4*)(a)     = *(const float4*)&As[kk][ty * 8];
            *(float4*)(a + 4) = *(const float4*)&As[kk][ty * 8 + 4];
            unsigned long long b2[4];
            {
                ulonglong2 bl0 = *(const ulonglong2*)&Bs[kk][tx * 8];
                ulonglong2 bl1 = *(const ulonglong2*)&Bs[kk][tx * 8 + 4];
                b2[0] = bl0.x; b2[1] = bl0.y; b2[2] = bl1.x; b2[3] = bl1.y;
            }
            #pragma unroll
            for (int i = 0; i < 8; i++) {
                unsigned long long a2;
                asm("mov.b64 %0, {%1, %1};" : "=l"(a2) : "r"(__float_as_uint(a[i])));
                #pragma unroll
                for (int j = 0; j < 4; j++)
                    asm("fma.rn.f32x2 %0, %1, %2, %0;"
                        : "+l"(acc2[i][j]) : "l"(a2), "l"(b2[j]));
            }
        }
        __syncthreads();
    }
    #pragma unroll
    for (int i = 0; i < 8; i++) {
        int mrow = m0 + ty * 8 + i;
        unsigned long long* dst =
            (unsigned long long*)&g_gpart[blockIdx.z][(size_t)mrow * FOURD + n0 + tx * 8];
        *(ulonglong2*)(dst)     = make_ulonglong2(acc2[i][0], acc2[i][1]);
        *(ulonglong2*)(dst + 2) = make_ulonglong2(acc2[i][2], acc2[i][3]);
    }
}

// ---------------- split segment attention: warp-autonomous, coalesced lane layout ----------------
// lane l owns columns {c*128 + l*4 .. +3} for chunk c in 0..3 (each LDG.128 is warp-contiguous 512B)
__global__ void k_attn_part(const float* __restrict__ x) {
    __shared__ __align__(16) float q_sh[D];
    __shared__ __align__(16) float rsh[NW][D];
    __shared__ float msh[NW], dsh[NW];

    int b  = blockIdx.x / SPLITS;
    int sp = blockIdx.x % SPLITS;
    int t = threadIdx.x;
    int w = t >> 5, lane = t & 31;

    int segs = g_segoff[b], sege = g_segoff[b + 1];
    int total = sege - segs;
    int start = segs + (int)(((long long)total * sp) / SPLITS);
    int end   = segs + (int)(((long long)total * (sp + 1)) / SPLITS);

    q_sh[t]       = g_qstar[b * QS + t];
    q_sh[t + 256] = g_qstar[b * QS + t + 256];
    __syncthreads();

    float qr[16];
    #pragma unroll
    for (int c = 0; c < 4; c++) {
        float4 qv = *(const float4*)&q_sh[c * 128 + lane * 4];
        qr[c * 4 + 0] = qv.x; qr[c * 4 + 1] = qv.y;
        qr[c * 4 + 2] = qv.z; qr[c * 4 + 3] = qv.w;
    }

    float m = -INFINITY, d = 0.0f;
    float r[16];
    #pragma unroll
    for (int j = 0; j < 16; j++) r[j] = 0.0f;

    int n = start + w;
    float4 xb0, xb1, xb2, xb3;
    if (n < end) {
        const float* p = x + (size_t)n * D;
        xb0 = ((const float4*)(p      ))[lane];
        xb1 = ((const float4*)(p + 128))[lane];
        xb2 = ((const float4*)(p + 256))[lane];
        xb3 = ((const float4*)(p + 384))[lane];
    }
    while (n < end) {
        float4 c0 = xb0, c1 = xb1, c2 = xb2, c3 = xb3;
        int nn = n + NW;
        if (nn < end) {
            const float* p = x + (size_t)nn * D;
            xb0 = ((const float4*)(p      ))[lane];
            xb1 = ((const float4*)(p + 128))[lane];
            xb2 = ((const float4*)(p + 256))[lane];
            xb3 = ((const float4*)(p + 384))[lane];
        }
        float s = c0.x * qr[0]  + c0.y * qr[1]  + c0.z * qr[2]  + c0.w * qr[3]
                + c1.x * qr[4]  + c1.y * qr[5]  + c1.z * qr[6]  + c1.w * qr[7]
                + c2.x * qr[8]  + c2.y * qr[9]  + c2.z * qr[10] + c2.w * qr[11]
                + c3.x * qr[12] + c3.y * qr[13] + c3.z * qr[14] + c3.w * qr[15];
        #pragma unroll
        for (int o = 16; o > 0; o >>= 1) s += __shfl_xor_sync(0xffffffffu, s, o);

        if (s > m) {
            float al = __expf(m - s);   // first iteration: exp(-inf) = 0
            d = d * al + 1.0f;
            r[0]  = r[0]  * al + c0.x;  r[1]  = r[1]  * al + c0.y;
            r[2]  = r[2]  * al + c0.z;  r[3]  = r[3]  * al + c0.w;
            r[4]  = r[4]  * al + c1.x;  r[5]  = r[5]  * al + c1.y;
            r[6]  = r[6]  * al + c1.z;  r[7]  = r[7]  * al + c1.w;
            r[8]  = r[8]  * al + c2.x;  r[9]  = r[9]  * al + c2.y;
            r[10] = r[10] * al + c2.z;  r[11] = r[11] * al + c2.w;
            r[12] = r[12] * al + c3.x;  r[13] = r[13] * al + c3.y;
            r[14] = r[14] * al + c3.z;  r[15] = r[15] * al + c3.w;
            m = s;
        } else {
            float wv = __expf(s - m);
            d += wv;
            r[0]  += wv * c0.x;  r[1]  += wv * c0.y;  r[2]  += wv * c0.z;  r[3]  += wv * c0.w;
            r[4]  += wv * c1.x;  r[5]  += wv * c1.y;  r[6]  += wv * c1.z;  r[7]  += wv * c1.w;
            r[8]  += wv * c2.x;  r[9]  += wv * c2.y;  r[10] += wv * c2.z;  r[11] += wv * c2.w;
            r[12] += wv * c3.x;  r[13] += wv * c3.y;  r[14] += wv * c3.z;  r[15] += wv * c3.w;
        }
        n = nn;
    }

    // per-warp partials to shared (canonical column order)
    if (lane == 0) { msh[w] = m; dsh[w] = d; }
    #pragma unroll
    for (int c = 0; c < 4; c++)
        *(float4*)&rsh[w][c * 128 + lane * 4] =
            make_float4(r[c * 4], r[c * 4 + 1], r[c * 4 + 2], r[c * 4 + 3]);
    __syncthreads();

    // block combine: thread t owns cols t and t+256
    float M = msh[0];
    #pragma unroll
    for (int p = 1; p < NW; p++) M = fmaxf(M, msh[p]);
    float Mg = isfinite(M) ? M : 0.0f;
    float dd = 0.0f, r0 = 0.0f, r1 = 0.0f;
    #pragma unroll
    for (int p = 0; p < NW; p++) {
        float sc = expf(msh[p] - Mg);
        dd += dsh[p] * sc;
        r0 += rsh[p][t] * sc;
        r1 += rsh[p][t + 256] * sc;
    }
    int pid = b * SPLITS + sp;
    g_pr[(size_t)pid * D + t]       = r0;
    g_pr[(size_t)pid * D + t + 256] = r1;
    if (t == 0) { g_pm[pid] = M; g_pd[pid] = dd; }
}

// ---------------- combine split partials -> r in g_qstar ----------------
__global__ void k_attn_combine() {
    __shared__ float sm[SPLITS], sd[SPLITS];
    int b = blockIdx.x, t = threadIdx.x;
    if (t < SPLITS) {
        sm[t] = g_pm[b * SPLITS + t];
        sd[t] = g_pd[b * SPLITS + t];
    }
    __syncthreads();
    float M = -INFINITY;
    #pragma unroll
    for (int p = 0; p < SPLITS; p++) M = fmaxf(M, sm[p]);
    if (!isfinite(M)) M = 0.0f;
    float denom = 0.0f;
    float scale[SPLITS];
    #pragma unroll
    for (int p = 0; p < SPLITS; p++) {
        scale[p] = expf(sm[p] - M);
        denom += sd[p] * scale[p];
    }
    float inv = 1.0f / (denom + 1e-16f);
    float r0 = 0.0f, r1 = 0.0f;
    #pragma unroll
    for (int p = 0; p < SPLITS; p++) {
        const float* pr = g_pr + (size_t)(b * SPLITS + p) * D;
        r0 += pr[t]       * scale[p];
        r1 += pr[t + 256] * scale[p];
    }
    g_qstar[b * QS + D + t]       = r0 * inv;
    g_qstar[b * QS + D + t + 256] = r1 * inv;
}

// ---------------- projection: out[b,o] = qstar[b,:] . W_proj[o,:] + b_proj[o] ----------------
__global__ void k_proj(const float* __restrict__ Wp, const float* __restrict__ bp,
                       float* __restrict__ out) {
    int gw = (blockIdx.x * 256 + threadIdx.x) >> 5;
    int lane = threadIdx.x & 31;
    int bb = gw >> 8, o = gw & 255;
    const float* qr = g_qstar + bb * QS;
    const float* wr = Wp + o * QS;
    float s = 0.0f;
    #pragma unroll
    for (int it = 0; it < QS / 128; it++) {
        int k = lane * 4 + it * 128;
        float4 a = *(const float4*)(qr + k);
        float4 w = *(const float4*)(wr + k);
        s += a.x * w.x + a.y * w.y + a.z * w.z + a.w * w.w;
    }
    #pragma unroll
    for (int off = 16; off > 0; off >>= 1) s += __shfl_xor_sync(0xffffffffu, s, off);
    if (lane == 0) out[gw] = s + bp[o];
}

// ---------------- launch ----------------
extern "C" void kernel_launch(void* const* d_in, const int* in_sizes, int n_in,
                              void* d_out, int out_size) {
    const float* x      = (const float*)d_in[0];
    const void*  batch  = d_in[1];
    const float* W_ih   = (const float*)d_in[2];
    const float* W_hh   = (const float*)d_in[3];
    const float* b_ih   = (const float*)d_in[4];
    const float* b_hh   = (const float*)d_in[5];
    const float* W_proj = (const float*)d_in[6];
    const float* b_proj = (const float*)d_in[7];
    (void)n_in; (void)out_size;
    int N = in_sizes[1];

    k_segscan<<<(N + 255) / 256, 256>>>(batch, N);
    k_wcomb<<<(FOURD * QS / 4 + 255) / 256, 256>>>(W_ih, W_hh, b_ih, b_hh);

    // step 0 (LSTM degenerates to biases)
    k_step0<<<(B * D + 255) / 256, 256>>>(b_ih, b_hh);
    k_attn_part<<<B * SPLITS, 256>>>(x);
    k_attn_combine<<<B, 256>>>();

    // steps 1,2
    for (int s = 1; s < 3; s++) {
        k_gemm_gates<<<dim3(FOURD / BN, B / BM, KSPLIT), 256>>>();
        k_lstm_ew<<<(B * D + 255) / 256, 256>>>();
        k_attn_part<<<B * SPLITS, 256>>>(x);
        k_attn_combine<<<B, 256>>>();
    }

    k_proj<<<(B * 256) / 8, 256>>>(W_proj, b_proj, (float*)d_out);
}